// round 9
// baseline (speedup 1.0000x reference)
#include <cuda_runtime.h>
#include <cuda_bf16.h>
#include <cstdint>

// Problem constants (fixed by setup_inputs)
#define B_   8
#define NS   5
#define NQ   128
#define T_   16
#define D_   2048
#define NROWS (B_*NQ)           // 1024
#define NCH  64                 // K chunks of 32 f32
#define PSTRIDE 257
#define NBLK 256

__device__ float g_rowterm[NROWS];
__device__ unsigned int g_done;   // zero-init; last block resets

#define LAM 0.1f
#define INVLAM 10.0f

__device__ __forceinline__ float softmin2(float a, float b) {
    float mn = fminf(a, b);
    return mn - LAM * __logf(1.0f + __expf(-fabsf(a - b) * INVLAM));
}
__device__ __forceinline__ float softmin3(float a, float b, float c) {
    float mn = fminf(fminf(a, b), c);
    float s = __expf((mn - a) * INVLAM) + __expf((mn - b) * INVLAM) + __expf((mn - c) * INVLAM);
    return mn - LAM * __logf(s);
}
__device__ __forceinline__ uint32_t smem_u32(const void* p) {
    uint32_t a;
    asm("{ .reg .u64 t; cvta.to.shared.u64 t, %1; cvt.u32.u64 %0, t; }" : "=r"(a) : "l"(p));
    return a;
}
__device__ __forceinline__ void ldsm4(uint32_t addr, uint32_t& r0, uint32_t& r1,
                                      uint32_t& r2, uint32_t& r3) {
    asm volatile("ldmatrix.sync.aligned.m8n8.x4.shared.b16 {%0,%1,%2,%3}, [%4];"
                 : "=r"(r0), "=r"(r1), "=r"(r2), "=r"(r3) : "r"(addr));
}
__device__ __forceinline__ uint2 cvt_u2(float4 v) {
    union { __nv_bfloat162 h; uint32_t u; } lo, hi;
    lo.h = __floats2bfloat162_rn(v.x, v.y);
    hi.h = __floats2bfloat162_rn(v.z, v.w);
    return make_uint2(lo.u, hi.u);
}
#define DOT4(v) ((v).x*(v).x + (v).y*(v).y + (v).z*(v).z + (v).w*(v).w)

#define MMA(ac, a0,a1,a2,a3, b0, b1) \
    asm volatile( \
        "mma.sync.aligned.m16n8k16.row.col.f32.bf16.bf16.f32 " \
        "{%0,%1,%2,%3}, {%4,%5,%6,%7}, {%8,%9}, {%0,%1,%2,%3};\n" \
        : "+f"((ac)[0]), "+f"((ac)[1]), "+f"((ac)[2]), "+f"((ac)[3]) \
        : "r"(a0), "r"(a1), "r"(a2), "r"(a3), "r"(b0), "r"(b1))

// ---------------- fused kernel ----------------
// CTA = (batch b, 64-query-row tile nt): 320 threads, 10 warps (5 M x 2 N).
// Tile rows 0..79 = supp, 80..143 = query. Double-buffered bf16 tiles (80B rows),
// 2-chunk-deep register prefetch. 2 CTAs/SM slip to cover DRAM latency.
__global__ __launch_bounds__(320, 2) void gemm_dtw_kernel(
        const float* __restrict__ supp, const float* __restrict__ query,
        const int* __restrict__ ys, float* __restrict__ out) {
    __shared__ __align__(16) char tiles[2][11520];    // also sDist after mainloop
    __shared__ float norm[144];
    __shared__ float t1s[20], t2s[20];
    __shared__ unsigned s_last;
    __shared__ float s_red[10];

    const int b = blockIdx.y, nt = blockIdx.x;
    const int tid = threadIdx.x, wid = tid >> 5, lane = tid & 31;
    const int wm = wid % 5;              // M warp tile (16 supp rows)
    const int wn = wid / 5;              // N warp tile (32 query cols)
    const int g = lane >> 2, t = lane & 3;
    const int quad = lane >> 3, qi = lane & 7;
    const uint32_t smb = smem_u32(tiles);

    // ldmatrix byte offsets within a tile
    const uint32_t offA  = (uint32_t)((wm*16 + qi + (quad & 1)*8) * 80 + (quad >> 1) * 16);
    const uint32_t offB0 = (uint32_t)((80 + wn*32 + (quad & 1)*8 + qi) * 80 + (quad >> 1) * 16);
    const uint32_t offB1 = offB0 + 16*80;

    // loader geometry: 8 threads/row; thread owns rows r, r+40, r+80, (r+120)
    const int r = tid >> 3, cs = tid & 7;
    const bool has3 = tid < 192;
    const float* gp0 = supp  + ((size_t)b*80 + r) * D_ + cs*4;
    const float* gp1 = gp0 + (size_t)40 * D_;
    const float* gp2 = query + ((size_t)b*2048 + nt*64 + r) * D_ + cs*4;
    const float* gp3 = gp2 + (size_t)40 * D_;     // deref only if has3
    const int bo0 = r*80 + cs*8;
    const int bo1 = bo0 + 40*80;
    const int bo2 = bo0 + 80*80;
    const int bo3 = bo0 + 120*80;

    float4 rs[2][4];
    float ss[4] = {0.f, 0.f, 0.f, 0.f};
    float acc[4][4];
    #pragma unroll
    for (int j = 0; j < 4; j++) { acc[j][0]=0.f; acc[j][1]=0.f; acc[j][2]=0.f; acc[j][3]=0.f; }

    #define LOADC(set, c) do { \
        rs[set][0] = *(const float4*)(gp0 + (c)*32); \
        rs[set][1] = *(const float4*)(gp1 + (c)*32); \
        rs[set][2] = *(const float4*)(gp2 + (c)*32); \
        if (has3) rs[set][3] = *(const float4*)(gp3 + (c)*32); } while(0)

    #define SUMSQC(set) do { \
        ss[0] += DOT4(rs[set][0]); ss[1] += DOT4(rs[set][1]); \
        ss[2] += DOT4(rs[set][2]); if (has3) ss[3] += DOT4(rs[set][3]); } while(0)

    #define STSC(set, stg) do { \
        char* bt = tiles[stg]; \
        *(uint2*)(bt + bo0) = cvt_u2(rs[set][0]); \
        *(uint2*)(bt + bo1) = cvt_u2(rs[set][1]); \
        *(uint2*)(bt + bo2) = cvt_u2(rs[set][2]); \
        if (has3) *(uint2*)(bt + bo3) = cvt_u2(rs[set][3]); } while(0)

    // ---- prologue: chunk 0 staged, chunk 1 in regs ----
    LOADC(0, 0);
    SUMSQC(0);
    STSC(0, 0);
    LOADC(1, 1);
    __syncthreads();

    // ---- mainloop ----
    #pragma unroll 1
    for (int c = 0; c < NCH; c++) {
        if (c < NCH - 2) LOADC(c & 1, c + 2);   // LDG 2 chunks ahead

        const uint32_t bufb = smb + (uint32_t)(c & 1) * 11520;
        #pragma unroll
        for (int ks = 0; ks < 2; ks++) {
            uint32_t a0, a1, a2, a3;
            ldsm4(bufb + offA + ks*32, a0, a1, a2, a3);
            uint32_t f0, f1, f2, f3, f4, f5, f6, f7;
            ldsm4(bufb + offB0 + ks*32, f0, f1, f2, f3);
            ldsm4(bufb + offB1 + ks*32, f4, f5, f6, f7);
            MMA(acc[0], a0,a1,a2,a3, f0, f2);
            MMA(acc[1], a0,a1,a2,a3, f1, f3);
            MMA(acc[2], a0,a1,a2,a3, f4, f6);
            MMA(acc[3], a0,a1,a2,a3, f5, f7);
        }

        if (c < NCH - 1) {
            SUMSQC((c + 1) & 1);
            STSC((c + 1) & 1, (c + 1) & 1);
        }
        __syncthreads();
    }

    // ---- deterministic 8-lane norm reduction ----
    #pragma unroll
    for (int o = 4; o; o >>= 1)
        #pragma unroll
        for (int s = 0; s < 4; s++)
            ss[s] += __shfl_xor_sync(0xffffffffu, ss[s], o);
    if ((tid & 7) == 0) {
        norm[r] = ss[0]; norm[r + 40] = ss[1]; norm[r + 80] = ss[2];
        if (has3) norm[r + 120] = ss[3];
    }
    __syncthreads();
    if (tid < 144) norm[tid] = rsqrtf(fmaxf(norm[tid], 1e-12f));
    __syncthreads();

    // ---- dist epilogue -> sDist (overwrites tiles; all ldsm done) ----
    float* sDist = (float*)tiles;
    #pragma unroll
    for (int jj = 0; jj < 2; jj++) {
        #pragma unroll
        for (int p = 0; p < 2; p++) {
            const int idx = jj*2 + p;
            #pragma unroll
            for (int c4 = 0; c4 < 4; c4++) {
                const int lr = wm*16 + g + (c4 >> 1)*8;              // supp row 0..79
                const int qc = wn*32 + jj*16 + p*8 + t*2 + (c4 & 1); // query col 0..63
                const int s = lr >> 4, l = lr & 15;
                const int ql = qc >> 4, m = qc & 15;
                const float dval = 1.0f - acc[idx][c4] * norm[lr] * norm[80 + qc];
                sDist[(ql*NS + s) * PSTRIDE + (l << 4) + m] = dval;
            }
        }
    }
    __syncthreads();

    // ---- soft-DTW: 40 threads, one (problem, direction) each ----
    if (tid < 40) {
        const int pb = tid >> 1, dir = tid & 1;
        const float* dm = sDist + pb * PSTRIDE;
        const int base = dir ? 255 : 0;
        const int sgn = dir ? -1 : 1;

        float prev[T_ + 2];
        prev[0] = 0.f;
        #pragma unroll
        for (int m = 1; m <= T_; m++) prev[m] = prev[m - 1] + dm[base + sgn * (m - 1)];
        prev[T_ + 1] = prev[T_];

        for (int l = 1; l < T_; l++) {
            const int rb = base + sgn * (l * 16);
            float drow[T_];
            #pragma unroll
            for (int m = 0; m < T_; m++) drow[m] = dm[rb + sgn * m];
            float left = 0.f;
            float dprev = prev[0];
            #pragma unroll
            for (int m = 1; m <= T_ + 1; m++) {
                const float up = prev[m];
                const float d = (m <= T_) ? drow[m - 1] : 0.f;
                float val;
                if (m == 1 || m == T_ + 1) val = softmin3(dprev, left, up) + d;
                else                        val = softmin2(dprev, left) + d;
                dprev = up;
                prev[m] = val;
                left = val;
            }
        }
        if (dir == 0) t1s[pb] = prev[T_ + 1];
        else          t2s[pb] = prev[T_ + 1];
    }
    __syncthreads();

    // ---- per-block outputs: tam (20) + per-query CE term (4 queries) ----
    if (tid < 20) {
        const int qloc = tid / NS, s = tid % NS;
        const int row = b * NQ + nt * 4 + qloc;
        out[1 + row * NS + s] = 0.5f * (t1s[tid] + t2s[tid]);
    }
    if (tid < 4) {
        const int row = b * NQ + nt * 4 + tid;
        float t1[NS], t2[NS];
        #pragma unroll
        for (int s = 0; s < NS; s++) { t1[s] = t1s[tid * NS + s]; t2[s] = t2s[tid * NS + s]; }
        float mx1 = -t1[0], mx2 = -t2[0];
        #pragma unroll
        for (int s = 1; s < NS; s++) { mx1 = fmaxf(mx1, -t1[s]); mx2 = fmaxf(mx2, -t2[s]); }
        float se1 = 0.f, se2 = 0.f;
        #pragma unroll
        for (int s = 0; s < NS; s++) { se1 += __expf(-t1[s] - mx1); se2 += __expf(-t2[s] - mx2); }
        const int y = ys[row];
        g_rowterm[row] = (mx1 + __logf(se1) + t1[y]) + (mx2 + __logf(se2) + t2[y]);
    }

    // ---- last block computes the final loss ----
    __threadfence();
    __syncthreads();
    if (tid == 0) s_last = (atomicAdd(&g_done, 1u) == (NBLK - 1u)) ? 1u : 0u;
    __syncthreads();
    if (s_last) {
        float v = g_rowterm[tid] + g_rowterm[tid + 320] + g_rowterm[tid + 640];
        if (tid < 64) v += g_rowterm[tid + 960];
        #pragma unroll
        for (int o = 16; o; o >>= 1) v += __shfl_xor_sync(0xffffffffu, v, o);
        if (lane == 0) s_red[wid] = v;
        __syncthreads();
        if (wid == 0) {
            float u = (lane < 10) ? s_red[lane] : 0.f;
            #pragma unroll
            for (int o = 8; o; o >>= 1) u += __shfl_xor_sync(0xffffffffu, u, o);
            if (lane == 0) { out[0] = 0.5f * u / (float)NROWS; g_done = 0u; }
        }
    }
}

// ---------------- launch ----------------
extern "C" void kernel_launch(void* const* d_in, const int* in_sizes, int n_in,
                              void* d_out, int out_size) {
    const float* supp  = (const float*)d_in[0];
    const float* query = (const float*)d_in[1];
    const int*   ys    = (const int*)d_in[2];
    float* out = (float*)d_out;

    gemm_dtw_kernel<<<dim3(32, B_), 320>>>(supp, query, ys, out);
}

// round 10
// speedup vs baseline: 1.0621x; 1.0621x over previous
#include <cuda_runtime.h>
#include <cuda_bf16.h>
#include <cstdint>

// Problem constants (fixed by setup_inputs)
#define B_   8
#define NS   5
#define NQ   128
#define T_   16
#define D_   2048
#define NROWS (B_*NQ)           // 1024
#define NCH  64                 // K chunks of 32 f32
#define PSTRIDE 257
#define NBLK 128
#define GT   640

// stage ring: 4 stages x (208 rows x 80B bf16)
#define STAGE_B   16640
#define RING_B    (4*STAGE_B)          // 66560
// overlay region (reuses ring after mainloop)
#define OFF_SDIST 0                    // 41120 B
#define OFF_SSP   41984                // 1664 f32 = 6656 B
#define OFF_NORM  48640                // 208 f32
#define OFF_T1    49472                // 40 f32
#define OFF_T2    49632                // 40 f32
#define SMEM_BYTES (RING_B + 64)

__device__ float g_rowterm[NROWS];
__device__ unsigned int g_done;

#define LAM 0.1f
#define INVLAM 10.0f

__device__ __forceinline__ float softmin2(float a, float b) {
    float mn = fminf(a, b);
    return mn - LAM * __logf(1.0f + __expf(-fabsf(a - b) * INVLAM));
}
__device__ __forceinline__ float softmin3(float a, float b, float c) {
    float mn = fminf(fminf(a, b), c);
    float s = __expf((mn - a) * INVLAM) + __expf((mn - b) * INVLAM) + __expf((mn - c) * INVLAM);
    return mn - LAM * __logf(s);
}
__device__ __forceinline__ uint32_t smem_u32(const void* p) {
    uint32_t a;
    asm("{ .reg .u64 t; cvta.to.shared.u64 t, %1; cvt.u32.u64 %0, t; }" : "=r"(a) : "l"(p));
    return a;
}
__device__ __forceinline__ void ldsm4(uint32_t addr, uint32_t& r0, uint32_t& r1,
                                      uint32_t& r2, uint32_t& r3) {
    asm volatile("ldmatrix.sync.aligned.m8n8.x4.shared.b16 {%0,%1,%2,%3}, [%4];"
                 : "=r"(r0), "=r"(r1), "=r"(r2), "=r"(r3) : "r"(addr));
}
__device__ __forceinline__ uint2 cvt_u2(float4 v) {
    union { __nv_bfloat162 h; uint32_t u; } lo, hi;
    lo.h = __floats2bfloat162_rn(v.x, v.y);
    hi.h = __floats2bfloat162_rn(v.z, v.w);
    return make_uint2(lo.u, hi.u);
}
#define DOT4(v) ((v).x*(v).x + (v).y*(v).y + (v).z*(v).z + (v).w*(v).w)
#define BAR_SYNC(id)   asm volatile("bar.sync %0, 640;"   :: "r"(id) : "memory")
#define BAR_ARRIVE(id) asm volatile("bar.arrive %0, 640;" :: "r"(id) : "memory")
// full[s] = 1+s, empty[s] = 5+s  (barrier 0 = __syncthreads)

// ---------------- fused kernel ----------------
// Block = (batch b, 128-query tile nt). Tile rows 0..79 supp, 80..207 query.
// Warps 10-19: producers (LDG f32 -> cvt bf16 -> STS, 2-chunk reg prefetch).
// Warps 0-9:   consumers (5M x 2N, ldmatrix + mma over full K).
__global__ __launch_bounds__(GT, 1) void gemm_dtw_kernel(
        const float* __restrict__ supp, const float* __restrict__ query,
        const int* __restrict__ ys, float* __restrict__ out) {
    extern __shared__ char smc[];
    float* sDist = (float*)(smc + OFF_SDIST);
    float* ssp   = (float*)(smc + OFF_SSP);
    float* norm  = (float*)(smc + OFF_NORM);
    float* t1s   = (float*)(smc + OFF_T1);
    float* t2s   = (float*)(smc + OFF_T2);
    __shared__ unsigned s_last;
    __shared__ float s_red[20];

    const int b = blockIdx.y, nt = blockIdx.x;
    const int tid = threadIdx.x, wid = tid >> 5, lane = tid & 31;
    const uint32_t smb = smem_u32(smc);

    if (wid >= 10) {
        // ================= PRODUCER =================
        const int ptid = tid - 320;              // 0..319
        // segments s_k = ptid + 320k, k=0..5 (k=5 only if ptid<64); 1664 total
        // segment s: row = s>>3 (0..207), f32 col = (s&7)*4
        const float* gp[6];
        int bo[6];
        bool act[6];
        #pragma unroll
        for (int k = 0; k < 6; k++) {
            const int s = ptid + 320*k;
            act[k] = (s < 1664);
            const int rr = act[k] ? (s >> 3) : 0;
            const int cc = (s & 7) * 4;
            gp[k] = (rr < 80)
                ? supp  + ((size_t)b*80 + rr) * D_ + cc
                : query + ((size_t)b*2048 + nt*128 + (rr - 80)) * D_ + cc;
            bo[k] = rr*80 + (s & 7)*8;
        }
        float4 rs[2][6];
        float ss[6] = {0.f,0.f,0.f,0.f,0.f,0.f};

        #define PLOAD(set, c) do { \
            _Pragma("unroll") \
            for (int k = 0; k < 5; k++) rs[set][k] = *(const float4*)(gp[k] + (c)*32); \
            if (act[5]) rs[set][5] = *(const float4*)(gp[5] + (c)*32); } while(0)

        PLOAD(0, 0);
        PLOAD(1, 1);

        #pragma unroll 1
        for (int c = 0; c < NCH; c++) {
            const int s = c & 3;
            const int set = c & 1;
            if (c >= 4) BAR_SYNC(5 + s);         // wait stage empty
            // sumsq (fixed order) + cvt + STS
            char* st = smc + s * STAGE_B;
            #pragma unroll
            for (int k = 0; k < 5; k++) {
                ss[k] += DOT4(rs[set][k]);
                *(uint2*)(st + bo[k]) = cvt_u2(rs[set][k]);
            }
            if (act[5]) {
                ss[5] += DOT4(rs[set][5]);
                *(uint2*)(st + bo[5]) = cvt_u2(rs[set][5]);
            }
            asm volatile("membar.cta;" ::: "memory");
            BAR_ARRIVE(1 + s);                   // signal stage full
            if (c + 2 < NCH) PLOAD(set, c + 2);  // prefetch 2 ahead
        }

        __syncthreads();                         // [A] mainloop done, ring reusable
        #pragma unroll
        for (int k = 0; k < 5; k++) ssp[ptid + 320*k] = ss[k];
        if (act[5]) ssp[ptid + 1600] = ss[5];
        __syncthreads();                         // [B]
        // (norm computed below by tid<208 — producers include tid 320..; skip)
        __syncthreads();                         // [C]
        __syncthreads();                         // [D] (dist epilogue done by consumers)
    } else {
        // ================= CONSUMER =================
        const int wm = wid % 5;                  // M warp tile (16 supp rows)
        const int wn = wid / 5;                  // N warp tile (64 query cols)
        const int g = lane >> 2, t = lane & 3;
        const int quad = lane >> 3, qi = lane & 7;

        const uint32_t offA = (uint32_t)((wm*16 + qi + (quad & 1)*8) * 80 + (quad >> 1) * 16);
        uint32_t offB[4];
        #pragma unroll
        for (int jj = 0; jj < 4; jj++)
            offB[jj] = (uint32_t)(6400 + (wn*64 + (2*jj + (quad >> 1))*8 + qi) * 80 + (quad & 1) * 16);

        float acc[8][4];
        #pragma unroll
        for (int j = 0; j < 8; j++) { acc[j][0]=0.f; acc[j][1]=0.f; acc[j][2]=0.f; acc[j][3]=0.f; }

        #pragma unroll 1
        for (int c = 0; c < NCH; c++) {
            const int s = c & 3;
            BAR_SYNC(1 + s);                     // wait stage full
            const uint32_t sb = smb + (uint32_t)s * STAGE_B;
            #pragma unroll
            for (int ks = 0; ks < 2; ks++) {
                uint32_t a0, a1, a2, a3;
                ldsm4(sb + offA + ks*32, a0, a1, a2, a3);
                uint32_t bf[16];
                #pragma unroll
                for (int jj = 0; jj < 4; jj++)
                    ldsm4(sb + offB[jj] + ks*32, bf[4*jj], bf[4*jj+1], bf[4*jj+2], bf[4*jj+3]);
                #pragma unroll
                for (int j = 0; j < 8; j++) {
                    asm volatile(
                        "mma.sync.aligned.m16n8k16.row.col.f32.bf16.bf16.f32 "
                        "{%0,%1,%2,%3}, {%4,%5,%6,%7}, {%8,%9}, {%0,%1,%2,%3};\n"
                        : "+f"(acc[j][0]), "+f"(acc[j][1]), "+f"(acc[j][2]), "+f"(acc[j][3])
                        : "r"(a0), "r"(a1), "r"(a2), "r"(a3), "r"(bf[2*j]), "r"(bf[2*j+1]));
                }
            }
            BAR_ARRIVE(5 + s);                   // signal stage empty (frags in regs)
        }

        __syncthreads();                         // [A]
        __syncthreads();                         // [B]
        if (tid < 208) {
            const float* sp = ssp + tid*8;
            float v = ((sp[0]+sp[1]) + (sp[2]+sp[3])) + ((sp[4]+sp[5]) + (sp[6]+sp[7]));
            norm[tid] = rsqrtf(fmaxf(v, 1e-12f));
        }
        __syncthreads();                         // [C] norms ready

        // dist epilogue -> sDist
        #pragma unroll
        for (int j = 0; j < 8; j++) {
            const int lc = wn * 64 + j * 8 + t * 2;
            #pragma unroll
            for (int half = 0; half < 2; half++) {
                const int lr = wm * 16 + g + half * 8;      // supp row 0..79
                const float invs = norm[lr];
                const int s = lr >> 4, l = lr & 15;
                #pragma unroll
                for (int e = 0; e < 2; e++) {
                    const int c = lc + e;                    // query col 0..127
                    const int ql = c >> 4, m = c & 15;
                    const int pb = ql * NS + s;
                    const float v = acc[j][half * 2 + e];
                    sDist[pb * PSTRIDE + (l << 4) + m] = 1.0f - v * invs * norm[80 + c];
                }
            }
        }
        __syncthreads();                         // [D]
    }

    // wait: [B] norm input ready was producer-side; align barrier counts:
    // producers executed syncs A,B,C,D; consumers A,B,C,D. Both aligned above.

    // ---- soft-DTW: 80 threads, one (problem, direction) each ----
    if (tid < 80) {
        const int pb = tid >> 1, dir = tid & 1;
        const float* dm = sDist + pb * PSTRIDE;
        const int base = dir ? 255 : 0;
        const int sgn = dir ? -1 : 1;

        float prev[T_ + 2];
        prev[0] = 0.f;
        #pragma unroll
        for (int m = 1; m <= T_; m++) prev[m] = prev[m - 1] + dm[base + sgn * (m - 1)];
        prev[T_ + 1] = prev[T_];

        for (int l = 1; l < T_; l++) {
            const int rb = base + sgn * (l * 16);
            float drow[T_];
            #pragma unroll
            for (int m = 0; m < T_; m++) drow[m] = dm[rb + sgn * m];
            float left = 0.f;
            float dprev = prev[0];
            #pragma unroll
            for (int m = 1; m <= T_ + 1; m++) {
                const float up = prev[m];
                const float d = (m <= T_) ? drow[m - 1] : 0.f;
                float val;
                if (m == 1 || m == T_ + 1) val = softmin3(dprev, left, up) + d;
                else                        val = softmin2(dprev, left) + d;
                dprev = up;
                prev[m] = val;
                left = val;
            }
        }
        if (dir == 0) t1s[pb] = prev[T_ + 1];
        else          t2s[pb] = prev[T_ + 1];
    }
    __syncthreads();

    // ---- per-block outputs: tam + per-query CE term ----
    if (tid < 40) {
        const int qloc = tid / NS, s = tid % NS;
        const int row = b * NQ + nt * 8 + qloc;
        out[1 + row * NS + s] = 0.5f * (t1s[tid] + t2s[tid]);
    }
    if (tid < 8) {
        const int row = b * NQ + nt * 8 + tid;
        float t1[NS], t2[NS];
        #pragma unroll
        for (int s = 0; s < NS; s++) { t1[s] = t1s[tid * NS + s]; t2[s] = t2s[tid * NS + s]; }
        float mx1 = -t1[0], mx2 = -t2[0];
        #pragma unroll
        for (int s = 1; s < NS; s++) { mx1 = fmaxf(mx1, -t1[s]); mx2 = fmaxf(mx2, -t2[s]); }
        float se1 = 0.f, se2 = 0.f;
        #pragma unroll
        for (int s = 0; s < NS; s++) { se1 += __expf(-t1[s] - mx1); se2 += __expf(-t2[s] - mx2); }
        const int y = ys[row];
        g_rowterm[row] = (mx1 + __logf(se1) + t1[y]) + (mx2 + __logf(se2) + t2[y]);
    }

    // ---- last block computes the final loss ----
    __threadfence();
    __syncthreads();
    if (tid == 0) s_last = (atomicAdd(&g_done, 1u) == (NBLK - 1u)) ? 1u : 0u;
    __syncthreads();
    if (s_last) {
        float v = 0.f;
        if (tid < 512) v = g_rowterm[tid] + g_rowterm[tid + 512];
        #pragma unroll
        for (int o = 16; o; o >>= 1) v += __shfl_xor_sync(0xffffffffu, v, o);
        if (lane == 0 && wid < 16) s_red[wid] = v;
        __syncthreads();
        if (wid == 0) {
            float u = (lane < 16) ? s_red[lane] : 0.f;
            #pragma unroll
            for (int o = 8; o; o >>= 1) u += __shfl_xor_sync(0xffffffffu, u, o);
            if (lane == 0) { out[0] = 0.5f * u / (float)NROWS; g_done = 0u; }
        }
    }
}

// ---------------- launch ----------------
extern "C" void kernel_launch(void* const* d_in, const int* in_sizes, int n_in,
                              void* d_out, int out_size) {
    const float* supp  = (const float*)d_in[0];
    const float* query = (const float*)d_in[1];
    const int*   ys    = (const int*)d_in[2];
    float* out = (float*)d_out;

    static bool attr_set = false;
    if (!attr_set) {
        cudaFuncSetAttribute(gemm_dtw_kernel,
                             cudaFuncAttributeMaxDynamicSharedMemorySize, SMEM_BYTES);
        attr_set = true;
    }

    gemm_dtw_kernel<<<dim3(16, B_), GT, SMEM_BYTES>>>(supp, query, ys, out);
}

// round 11
// speedup vs baseline: 2.0587x; 1.9383x over previous
#include <cuda_runtime.h>
#include <cuda_bf16.h>
#include <cstdint>

// Problem constants (fixed by setup_inputs)
#define B_   8
#define NS   5
#define NQ   128
#define T_   16
#define D_   2048
#define NROWS (B_*NQ)           // 1024

__device__ float g_rowterm[NROWS];
__device__ unsigned int g_done;   // zero-init; last block resets

#define LAM 0.1f
#define INVLAM 10.0f

__device__ __forceinline__ float softmin2(float a, float b) {
    float mn = fminf(a, b);
    return mn - LAM * __logf(1.0f + __expf(-fabsf(a - b) * INVLAM));
}
__device__ __forceinline__ float softmin3(float a, float b, float c) {
    float mn = fminf(fminf(a, b), c);
    float s = __expf((mn - a) * INVLAM) + __expf((mn - b) * INVLAM) + __expf((mn - c) * INVLAM);
    return mn - LAM * __logf(s);
}

__device__ __forceinline__ uint32_t smem_u32(const void* p) {
    uint32_t a;
    asm("{ .reg .u64 t; cvta.to.shared.u64 t, %1; cvt.u32.u64 %0, t; }" : "=r"(a) : "l"(p));
    return a;
}
__device__ __forceinline__ void ldsm4(uint32_t addr, uint32_t& r0, uint32_t& r1,
                                      uint32_t& r2, uint32_t& r3) {
    asm volatile("ldmatrix.sync.aligned.m8n8.x4.shared.b16 {%0,%1,%2,%3}, [%4];"
                 : "=r"(r0), "=r"(r1), "=r"(r2), "=r"(r3) : "r"(addr));
}
// f32x4 -> packed bf16x4 (two u32)
__device__ __forceinline__ uint2 cvt_u2(float4 v) {
    union { __nv_bfloat162 h; uint32_t u; } lo, hi;
    lo.h = __floats2bfloat162_rn(v.x, v.y);
    hi.h = __floats2bfloat162_rn(v.z, v.w);
    return make_uint2(lo.u, hi.u);
}

// ---------------- fused kernel: GEMM (split-K x2) -> cosine dist -> soft-DTW -> CE ----------------
#define BM 80
#define BN 128
#define BK 32
#define LDA 40        // smem row stride in bf16 (80 B)
#define GT 640        // 20 warps: 2 K-groups x (5 M x 2 N)
#define PSTRIDE 257

#define ABYTES (BM*LDA*2)         // 6400
#define BBYTES (BN*LDA*2)         // 10240
#define SB_BASE (4*ABYTES)        // 25600

#define ACCBUF_F 10560
#define SMEM_BYTES (25600 + 40960 + ACCBUF_F*4 + (256+160+80)*4)

__global__ __launch_bounds__(GT, 1) void gemm_dtw_kernel(
        const float* __restrict__ supp, const float* __restrict__ query,
        const int* __restrict__ ys, float* __restrict__ out) {
    extern __shared__ char smc[];
    __nv_bfloat16* sA = (__nv_bfloat16*)smc;                  // [2kg][2stage][BM*LDA]
    __nv_bfloat16* sB = sA + 4 * BM * LDA;                    // [2kg][2stage][BN*LDA]
    float* accbuf = (float*)(sB + 4 * BN * LDA);              // 10560 f32 (later sDist)
    float* sDist  = accbuf;
    float* qsum   = accbuf + ACCBUF_F;                        // [2][128]
    float* ssum   = qsum + 256;                               // [2][80]
    float* t1s    = ssum + 160;                               // [40]
    float* t2s    = t1s + 40;                                 // [40]

    const int b = blockIdx.y, nt = blockIdx.x;
    const int tid = threadIdx.x, wid = tid >> 5, lane = tid & 31;
    const int kg = wid >= 10;            // K-split group
    const int gtid = tid - kg * 320;
    const int gwid = wid - kg * 10;
    const float* Ag = supp  + (size_t)b * BM * D_;
    const float* Bg = query + ((size_t)b * (NQ*T_) + (size_t)nt * BN) * D_;

    float acc[8][4];
    #pragma unroll
    for (int j = 0; j < 8; j++) { acc[j][0]=0.f; acc[j][1]=0.f; acc[j][2]=0.f; acc[j][3]=0.f; }

    const int wm = gwid % 5;             // M warp tile (16 rows)
    const int wn = gwid / 5;             // N warp tile (64 cols)
    const int g  = lane >> 2, t = lane & 3;
    const int quad = lane >> 3, qi = lane & 7;

    __nv_bfloat16* sAg = sA + kg * (2 * BM * LDA);
    __nv_bfloat16* sBg = sB + kg * (2 * BN * LDA);

    // ---- ldmatrix per-lane byte offsets ----
    const uint32_t smb = smem_u32(smc);
    const uint32_t smbA = smb + kg * (2 * ABYTES);
    const uint32_t smbB = smb + SB_BASE + kg * (2 * BBYTES);
    const uint32_t offA = (uint32_t)((wm*16 + qi + (quad & 1)*8) * (LDA*2) + (quad >> 1) * 16);
    uint32_t offB[4];
    #pragma unroll
    for (int jj = 0; jj < 4; jj++)
        offB[jj] = (uint32_t)((wn*64 + (2*jj + (quad >> 1))*8 + qi) * (LDA*2) + (quad & 1) * 16);

    // per-group loader coordinates (each row covered by one aligned 8-lane group)
    const int ar0 = gtid >> 3,        ac0 = (gtid & 7) * 4;
    const int ar1 = (gtid+320) >> 3,  ac1 = ((gtid+320) & 7) * 4;
    const int br0 = gtid >> 3,        bc0 = (gtid & 7) * 4;
    const int br1 = (gtid+320) >> 3,  bc1 = ((gtid+320) & 7) * 4;
    const int br2 = (gtid+640) >> 3,  bc2 = ((gtid+640) & 7) * 4;
    const int br3 = (gtid+960) >> 3,  bc3 = ((gtid+960) & 7) * 4;
    const bool b3ok = (gtid + 960) < BN * 8;

    float4 ra0, ra1, rb0, rb1, rb2, rb3;
    rb3.x = rb3.y = rb3.z = rb3.w = 0.f;

    float as0 = 0.f, as1 = 0.f, qs0 = 0.f, qs1 = 0.f, qs2 = 0.f, qs3 = 0.f;
    #define DOT4(v) ((v).x*(v).x + (v).y*(v).y + (v).z*(v).z + (v).w*(v).w)

    #define LDG_CHUNK(k0) do { \
        ra0 = *(const float4*)(Ag + (size_t)ar0*D_ + (k0) + ac0); \
        ra1 = *(const float4*)(Ag + (size_t)ar1*D_ + (k0) + ac1); \
        rb0 = *(const float4*)(Bg + (size_t)br0*D_ + (k0) + bc0); \
        rb1 = *(const float4*)(Bg + (size_t)br1*D_ + (k0) + bc1); \
        rb2 = *(const float4*)(Bg + (size_t)br2*D_ + (k0) + bc2); \
        if (b3ok) rb3 = *(const float4*)(Bg + (size_t)br3*D_ + (k0) + bc3); } while(0)

    #define SUMSQ_CHUNK() do { \
        as0 += DOT4(ra0); as1 += DOT4(ra1); \
        qs0 += DOT4(rb0); qs1 += DOT4(rb1); qs2 += DOT4(rb2); qs3 += DOT4(rb3); } while(0)

    #define STS_CHUNK(stg) do { \
        const int nbA = (stg) * BM * LDA; \
        const int nbB = (stg) * BN * LDA; \
        *(uint2*)&sAg[nbA + ar0*LDA + ac0] = cvt_u2(ra0); \
        *(uint2*)&sAg[nbA + ar1*LDA + ac1] = cvt_u2(ra1); \
        *(uint2*)&sBg[nbB + br0*LDA + bc0] = cvt_u2(rb0); \
        *(uint2*)&sBg[nbB + br1*LDA + bc1] = cvt_u2(rb1); \
        *(uint2*)&sBg[nbB + br2*LDA + bc2] = cvt_u2(rb2); \
        if (b3ok) *(uint2*)&sBg[nbB + br3*LDA + bc3] = cvt_u2(rb3); } while(0)

    #define GBAR() asm volatile("bar.sync %0, %1;" :: "r"(kg + 1), "r"(320) : "memory")

    const int NIT = (D_ / BK) / 2;   // 32 chunks per group

    // ---- prologue: chunk 0 (kc=kg) staged into buf0; chunk 1 (kc=kg+2) in regs ----
    LDG_CHUNK(kg * BK);
    SUMSQ_CHUNK();
    STS_CHUNK(0);
    LDG_CHUNK((kg + 2) * BK);
    GBAR();

    // ---- mainloop: STS-first scheduling (LDG -> STS spans a full iteration) ----
    #pragma unroll 1
    for (int i = 0; i < NIT; i++) {
        // stage chunk i+1 (regs loaded during iter i-1 / prologue)
        if (i + 1 < NIT) {
            SUMSQ_CHUNK();
            STS_CHUNK((i + 1) & 1);
        }
        // issue LDG for chunk i+2 into the (now-consumed) reg set
        if (i + 2 < NIT) LDG_CHUNK((kg + 2 * (i + 2)) * BK);

        // compute on buf (i&1)
        const uint32_t aB = smbA + (uint32_t)(i & 1) * ABYTES + offA;
        const uint32_t bB = smbB + (uint32_t)(i & 1) * BBYTES;
        #pragma unroll
        for (int ks = 0; ks < 2; ks++) {
            uint32_t a0, a1, a2, a3;
            ldsm4(aB + ks * 32, a0, a1, a2, a3);
            uint32_t bf[16];
            #pragma unroll
            for (int jj = 0; jj < 4; jj++)
                ldsm4(bB + offB[jj] + ks * 32, bf[4*jj], bf[4*jj+1], bf[4*jj+2], bf[4*jj+3]);
            #pragma unroll
            for (int j = 0; j < 8; j++) {
                asm volatile(
                    "mma.sync.aligned.m16n8k16.row.col.f32.bf16.bf16.f32 "
                    "{%0,%1,%2,%3}, {%4,%5,%6,%7}, {%8,%9}, {%0,%1,%2,%3};\n"
                    : "+f"(acc[j][0]), "+f"(acc[j][1]), "+f"(acc[j][2]), "+f"(acc[j][3])
                    : "r"(a0), "r"(a1), "r"(a2), "r"(a3), "r"(bf[2*j]), "r"(bf[2*j+1]));
            }
        }
        GBAR();
    }

    // ---- per-group deterministic 8-lane reduction of sum-of-squares ----
    #pragma unroll
    for (int o = 4; o; o >>= 1) {
        as0 += __shfl_xor_sync(0xffffffffu, as0, o);
        as1 += __shfl_xor_sync(0xffffffffu, as1, o);
        qs0 += __shfl_xor_sync(0xffffffffu, qs0, o);
        qs1 += __shfl_xor_sync(0xffffffffu, qs1, o);
        qs2 += __shfl_xor_sync(0xffffffffu, qs2, o);
        qs3 += __shfl_xor_sync(0xffffffffu, qs3, o);
    }
    if ((gtid & 7) == 0) {
        ssum[kg*80 + ar0] = as0; ssum[kg*80 + ar1] = as1;
        qsum[kg*128 + br0] = qs0; qsum[kg*128 + br1] = qs1; qsum[kg*128 + br2] = qs2;
        if (b3ok) qsum[kg*128 + br3] = qs3;
    }

    // ---- kg=1 dumps acc (stride-33 conflict-free layout) ----
    if (kg == 1) {
        float* ab = accbuf + gwid * 1056 + lane;
        #pragma unroll
        for (int j = 0; j < 8; j++)
            #pragma unroll
            for (int c = 0; c < 4; c++)
                ab[(j*4 + c) * 33] = acc[j][c];
    }
    __syncthreads();

    // ---- kg=0: reduce + combine norms ----
    if (kg == 0) {
        const float* ab = accbuf + gwid * 1056 + lane;
        #pragma unroll
        for (int j = 0; j < 8; j++)
            #pragma unroll
            for (int c = 0; c < 4; c++)
                acc[j][c] += ab[(j*4 + c) * 33];
    }
    if (tid < BN)            qsum[tid] = rsqrtf(fmaxf(qsum[tid] + qsum[128 + tid], 1e-12f));
    else if (tid < BN + BM)  ssum[tid - BN] = rsqrtf(fmaxf(ssum[tid - BN] + ssum[80 + tid - BN], 1e-12f));
    __syncthreads();

    // ---- epilogue: dist into smem (kg=0 only) ----
    if (kg == 0) {
        #pragma unroll
        for (int j = 0; j < 8; j++) {
            const int lc = wn * 64 + j * 8 + t * 2;
            #pragma unroll
            for (int half = 0; half < 2; half++) {
                const int lr = wm * 16 + g + half * 8;      // 0..79
                const float invs = ssum[lr];
                const int s = lr >> 4, l = lr & 15;
                #pragma unroll
                for (int e = 0; e < 2; e++) {
                    const int c = lc + e;                    // local col 0..127
                    const int qloc = c >> 4, m = c & 15;
                    const int pb = qloc * NS + s;            // 0..39
                    const float v = acc[j][half * 2 + e];
                    sDist[pb * PSTRIDE + (l << 4) + m] = 1.0f - v * invs * qsum[c];
                }
            }
        }
    }
    __syncthreads();

    // ---- soft-DTW: 80 threads, one (problem, direction) each ----
    if (tid < 80) {
        const int pb = tid >> 1, dir = tid & 1;
        const float* dm = sDist + pb * PSTRIDE;
        const int base = dir ? 255 : 0;
        const int sgn = dir ? -1 : 1;

        float prev[T_ + 2];
        prev[0] = 0.f;
        #pragma unroll
        for (int m = 1; m <= T_; m++) prev[m] = prev[m - 1] + dm[base + sgn * (m - 1)];
        prev[T_ + 1] = prev[T_];

        for (int l = 1; l < T_; l++) {
            const int rb = base + sgn * (l * 16);
            float drow[T_];
            #pragma unroll
            for (int m = 0; m < T_; m++) drow[m] = dm[rb + sgn * m];
            float left = 0.f;
            float dprev = prev[0];
            #pragma unroll
            for (int m = 1; m <= T_ + 1; m++) {
                const float up = prev[m];
                const float d = (m <= T_) ? drow[m - 1] : 0.f;
                float val;
                if (m == 1 || m == T_ + 1) val = softmin3(dprev, left, up) + d;
                else                        val = softmin2(dprev, left) + d;
                dprev = up;
                prev[m] = val;
                left = val;
            }
        }
        if (dir == 0) t1s[pb] = prev[T_ + 1];
        else          t2s[pb] = prev[T_ + 1];
    }
    __syncthreads();

    // ---- per-block outputs: tam + per-query CE term ----
    if (tid < 40) {
        const int qloc = tid / NS, s = tid % NS;
        const int row = b * NQ + nt * 8 + qloc;
        out[1 + row * NS + s] = 0.5f * (t1s[tid] + t2s[tid]);
    }
    if (tid < 8) {
        const int row = b * NQ + nt * 8 + tid;
        float t1[NS], t2[NS];
        #pragma unroll
        for (int s = 0; s < NS; s++) { t1[s] = t1s[tid * NS + s]; t2[s] = t2s[tid * NS + s]; }
        float mx1 = -t1[0], mx2 = -t2[0];
        #pragma unroll
        for (int s = 1; s < NS; s++) { mx1 = fmaxf(mx1, -t1[s]); mx2 = fmaxf(mx2, -t2[s]); }
        float se1 = 0.f, se2 = 0.f;
        #pragma unroll
        for (int s = 0; s < NS; s++) { se1 += __expf(-t1[s] - mx1); se2 += __expf(-t2[s] - mx2); }
        const int y = ys[row];
        g_rowterm[row] = (mx1 + __logf(se1) + t1[y]) + (mx2 + __logf(se2) + t2[y]);
    }

    // ---- last block computes the final loss ----
    __shared__ unsigned s_last;
    __shared__ float s_red[20];
    __threadfence();
    __syncthreads();
    if (tid == 0) s_last = (atomicAdd(&g_done, 1u) == 127u) ? 1u : 0u;
    __syncthreads();
    if (s_last) {
        float v = 0.f;
        if (tid < 512) v = g_rowterm[tid] + g_rowterm[tid + 512];
        #pragma unroll
        for (int o = 16; o; o >>= 1) v += __shfl_xor_sync(0xffffffffu, v, o);
        if (lane == 0 && wid < 16) s_red[wid] = v;
        __syncthreads();
        if (wid == 0) {
            float u = (lane < 16) ? s_red[lane] : 0.f;
            #pragma unroll
            for (int o = 8; o; o >>= 1) u += __shfl_xor_sync(0xffffffffu, u, o);
            if (lane == 0) { out[0] = 0.5f * u / (float)NROWS; g_done = 0u; }
        }
    }
}

// ---------------- launch ----------------
extern "C" void kernel_launch(void* const* d_in, const int* in_sizes, int n_in,
                              void* d_out, int out_size) {
    const float* supp  = (const float*)d_in[0];
    const float* query = (const float*)d_in[1];
    const int*   ys    = (const int*)d_in[2];
    float* out = (float*)d_out;

    static bool attr_set = false;
    if (!attr_set) {
        cudaFuncSetAttribute(gemm_dtw_kernel,
                             cudaFuncAttributeMaxDynamicSharedMemorySize, SMEM_BYTES);
        attr_set = true;
    }

    gemm_dtw_kernel<<<dim3(16, B_), GT, SMEM_BYTES>>>(supp, query, ys, out);
}

// round 12
// speedup vs baseline: 2.0834x; 1.0120x over previous
#include <cuda_runtime.h>
#include <cuda_bf16.h>
#include <cstdint>

// Problem constants (fixed by setup_inputs)
#define B_   8
#define NS   5
#define NQ   128
#define T_   16
#define D_   2048
#define NROWS (B_*NQ)           // 1024

__device__ float g_rowterm[NROWS];
__device__ unsigned int g_done;   // zero-init; last block resets

#define LAM 0.1f
#define INVLAM 10.0f

__device__ __forceinline__ float softmin2(float a, float b) {
    float mn = fminf(a, b);
    return mn - LAM * __logf(1.0f + __expf(-fabsf(a - b) * INVLAM));
}
__device__ __forceinline__ float softmin3(float a, float b, float c) {
    float mn = fminf(fminf(a, b), c);
    float s = __expf((mn - a) * INVLAM) + __expf((mn - b) * INVLAM) + __expf((mn - c) * INVLAM);
    return mn - LAM * __logf(s);
}

__device__ __forceinline__ uint32_t smem_u32(const void* p) {
    uint32_t a;
    asm("{ .reg .u64 t; cvta.to.shared.u64 t, %1; cvt.u32.u64 %0, t; }" : "=r"(a) : "l"(p));
    return a;
}
__device__ __forceinline__ void ldsm4(uint32_t addr, uint32_t& r0, uint32_t& r1,
                                      uint32_t& r2, uint32_t& r3) {
    asm volatile("ldmatrix.sync.aligned.m8n8.x4.shared.b16 {%0,%1,%2,%3}, [%4];"
                 : "=r"(r0), "=r"(r1), "=r"(r2), "=r"(r3) : "r"(addr));
}
// f32x4 -> packed bf16x4 (two u32)
__device__ __forceinline__ uint2 cvt_u2(float4 v) {
    union { __nv_bfloat162 h; uint32_t u; } lo, hi;
    lo.h = __floats2bfloat162_rn(v.x, v.y);
    hi.h = __floats2bfloat162_rn(v.z, v.w);
    return make_uint2(lo.u, hi.u);
}

// ---------------- fused kernel: GEMM (split-K x2) -> cosine dist -> soft-DTW -> CE ----------------
#define BM 80
#define BN 128
#define BK 32
#define LDA 40        // smem row stride in bf16 (80 B)
#define GT 640        // 20 warps: 2 K-groups x (5 M x 2 N)
#define PSTRIDE 257

#define ABYTES (BM*LDA*2)         // 6400
#define BBYTES (BN*LDA*2)         // 10240
#define AB4 (4*ABYTES)            // per-kg A region (4 stages) 25600
#define BB4 (4*BBYTES)            // per-kg B region (4 stages) 40960
#define SB_BASE (2*AB4)           // 51200
#define OFF_ACC (SB_BASE + 2*BB4) // 133120

#define ACCBUF_F 10560
#define SMEM_BYTES (OFF_ACC + ACCBUF_F*4 + (256+160+80)*4)

__global__ __launch_bounds__(GT, 1) void gemm_dtw_kernel(
        const float* __restrict__ supp, const float* __restrict__ query,
        const int* __restrict__ ys, float* __restrict__ out) {
    extern __shared__ char smc[];
    float* accbuf = (float*)(smc + OFF_ACC);                  // 10560 f32 (later sDist)
    float* sDist  = accbuf;
    float* qsum   = accbuf + ACCBUF_F;                        // [2][128]
    float* ssum   = qsum + 256;                               // [2][80]
    float* t1s    = ssum + 160;                               // [40]
    float* t2s    = t1s + 40;                                 // [40]

    const int b = blockIdx.y, nt = blockIdx.x;
    const int tid = threadIdx.x, wid = tid >> 5, lane = tid & 31;
    const int kg = wid >= 10;            // K-split group
    const int gtid = tid - kg * 320;
    const int gwid = wid - kg * 10;
    const float* Ag = supp  + (size_t)b * BM * D_;
    const float* Bg = query + ((size_t)b * (NQ*T_) + (size_t)nt * BN) * D_;

    float acc[8][4];
    #pragma unroll
    for (int j = 0; j < 8; j++) { acc[j][0]=0.f; acc[j][1]=0.f; acc[j][2]=0.f; acc[j][3]=0.f; }

    const int wm = gwid % 5;             // M warp tile (16 rows)
    const int wn = gwid / 5;             // N warp tile (64 cols)
    const int g  = lane >> 2, t = lane & 3;
    const int quad = lane >> 3, qi = lane & 7;

    // ---- smem byte bases ----
    const uint32_t smb = smem_u32(smc);
    const uint32_t smbA = smb + kg * AB4;
    const uint32_t smbB = smb + SB_BASE + kg * BB4;
    char* const scA = smc + kg * AB4;
    char* const scB = smc + SB_BASE + kg * BB4;

    const uint32_t offA = (uint32_t)((wm*16 + qi + (quad & 1)*8) * (LDA*2) + (quad >> 1) * 16);
    uint32_t offB[4];
    #pragma unroll
    for (int jj = 0; jj < 4; jj++)
        offB[jj] = (uint32_t)((wn*64 + (2*jj + (quad >> 1))*8 + qi) * (LDA*2) + (quad & 1) * 16);

    // per-group loader coordinates (each row covered by one aligned 8-lane group)
    const int ar0 = gtid >> 3,        ac0 = (gtid & 7) * 4;
    const int ar1 = (gtid+320) >> 3,  ac1 = ((gtid+320) & 7) * 4;
    const int br0 = gtid >> 3,        bc0 = (gtid & 7) * 4;
    const int br1 = (gtid+320) >> 3,  bc1 = ((gtid+320) & 7) * 4;
    const int br2 = (gtid+640) >> 3,  bc2 = ((gtid+640) & 7) * 4;
    const int br3 = (gtid+960) >> 3,  bc3 = ((gtid+960) & 7) * 4;
    const bool b3ok = (gtid + 960) < BN * 8;

    float4 ra0, ra1, rb0, rb1, rb2, rb3;
    rb3.x = rb3.y = rb3.z = rb3.w = 0.f;

    float as0 = 0.f, as1 = 0.f, qs0 = 0.f, qs1 = 0.f, qs2 = 0.f, qs3 = 0.f;
    #define DOT4(v) ((v).x*(v).x + (v).y*(v).y + (v).z*(v).z + (v).w*(v).w)

    #define LDG_CHUNK(k0) do { \
        ra0 = *(const float4*)(Ag + (size_t)ar0*D_ + (k0) + ac0); \
        ra1 = *(const float4*)(Ag + (size_t)ar1*D_ + (k0) + ac1); \
        rb0 = *(const float4*)(Bg + (size_t)br0*D_ + (k0) + bc0); \
        rb1 = *(const float4*)(Bg + (size_t)br1*D_ + (k0) + bc1); \
        rb2 = *(const float4*)(Bg + (size_t)br2*D_ + (k0) + bc2); \
        if (b3ok) rb3 = *(const float4*)(Bg + (size_t)br3*D_ + (k0) + bc3); } while(0)

    #define SUMSQ_CHUNK() do { \
        as0 += DOT4(ra0); as1 += DOT4(ra1); \
        qs0 += DOT4(rb0); qs1 += DOT4(rb1); qs2 += DOT4(rb2); qs3 += DOT4(rb3); } while(0)

    #define STS_CHUNK(stg) do { \
        char* bA = scA + (stg) * ABYTES; \
        char* bB = scB + (stg) * BBYTES; \
        *(uint2*)(bA + (ar0*LDA + ac0)*2) = cvt_u2(ra0); \
        *(uint2*)(bA + (ar1*LDA + ac1)*2) = cvt_u2(ra1); \
        *(uint2*)(bB + (br0*LDA + bc0)*2) = cvt_u2(rb0); \
        *(uint2*)(bB + (br1*LDA + bc1)*2) = cvt_u2(rb1); \
        *(uint2*)(bB + (br2*LDA + bc2)*2) = cvt_u2(rb2); \
        if (b3ok) *(uint2*)(bB + (br3*LDA + bc3)*2) = cvt_u2(rb3); } while(0)

    #define MMA_SECTION(stg) do { \
        const uint32_t aB = smbA + (uint32_t)(stg) * ABYTES + offA; \
        const uint32_t bB = smbB + (uint32_t)(stg) * BBYTES; \
        _Pragma("unroll") \
        for (int ks = 0; ks < 2; ks++) { \
            uint32_t a0, a1, a2, a3; \
            ldsm4(aB + ks * 32, a0, a1, a2, a3); \
            uint32_t bf[16]; \
            _Pragma("unroll") \
            for (int jj = 0; jj < 4; jj++) \
                ldsm4(bB + offB[jj] + ks * 32, bf[4*jj], bf[4*jj+1], bf[4*jj+2], bf[4*jj+3]); \
            _Pragma("unroll") \
            for (int j = 0; j < 8; j++) { \
                asm volatile( \
                    "mma.sync.aligned.m16n8k16.row.col.f32.bf16.bf16.f32 " \
                    "{%0,%1,%2,%3}, {%4,%5,%6,%7}, {%8,%9}, {%0,%1,%2,%3};\n" \
                    : "+f"(acc[j][0]), "+f"(acc[j][1]), "+f"(acc[j][2]), "+f"(acc[j][3]) \
                    : "r"(a0), "r"(a1), "r"(a2), "r"(a3), "r"(bf[2*j]), "r"(bf[2*j+1])); \
            } \
        } } while(0)

    #define GBAR() asm volatile("bar.sync %0, %1;" :: "r"(kg + 1), "r"(320) : "memory")

    // group chunk c (0..31) sits at global K offset (kg + 2c)*BK

    // ---- prologue: chunks 0,1 staged; chunk 2 in regs ----
    LDG_CHUNK(kg * BK);
    SUMSQ_CHUNK();
    STS_CHUNK(0);
    LDG_CHUNK((kg + 2) * BK);
    SUMSQ_CHUNK();
    STS_CHUNK(1);
    LDG_CHUNK((kg + 4) * BK);
    GBAR();

    // ---- mainloop: 16 double-chunk iterations, one barrier each ----
    #pragma unroll 1
    for (int i = 0; i < 16; i++) {
        if (i < 15) {                     // stage chunk 2i+2 (regs from prev iter)
            SUMSQ_CHUNK();
            STS_CHUNK((2*i + 2) & 3);
            LDG_CHUNK((kg + 2*(2*i + 3)) * BK);
        }
        MMA_SECTION((2*i) & 3);
        if (i < 15) {                     // stage chunk 2i+3 (regs from this iter)
            SUMSQ_CHUNK();
            STS_CHUNK((2*i + 3) & 3);
        }
        if (i < 14) LDG_CHUNK((kg + 2*(2*i + 4)) * BK);
        MMA_SECTION((2*i + 1) & 3);
        GBAR();
    }

    // ---- per-group deterministic 8-lane reduction of sum-of-squares ----
    #pragma unroll
    for (int o = 4; o; o >>= 1) {
        as0 += __shfl_xor_sync(0xffffffffu, as0, o);
        as1 += __shfl_xor_sync(0xffffffffu, as1, o);
        qs0 += __shfl_xor_sync(0xffffffffu, qs0, o);
        qs1 += __shfl_xor_sync(0xffffffffu, qs1, o);
        qs2 += __shfl_xor_sync(0xffffffffu, qs2, o);
        qs3 += __shfl_xor_sync(0xffffffffu, qs3, o);
    }
    if ((gtid & 7) == 0) {
        ssum[kg*80 + ar0] = as0; ssum[kg*80 + ar1] = as1;
        qsum[kg*128 + br0] = qs0; qsum[kg*128 + br1] = qs1; qsum[kg*128 + br2] = qs2;
        if (b3ok) qsum[kg*128 + br3] = qs3;
    }

    // ---- kg=1 dumps acc (stride-33 conflict-free layout) ----
    if (kg == 1) {
        float* ab = accbuf + gwid * 1056 + lane;
        #pragma unroll
        for (int j = 0; j < 8; j++)
            #pragma unroll
            for (int c = 0; c < 4; c++)
                ab[(j*4 + c) * 33] = acc[j][c];
    }
    __syncthreads();

    // ---- kg=0: reduce + combine norms ----
    if (kg == 0) {
        const float* ab = accbuf + gwid * 1056 + lane;
        #pragma unroll
        for (int j = 0; j < 8; j++)
            #pragma unroll
            for (int c = 0; c < 4; c++)
                acc[j][c] += ab[(j*4 + c) * 33];
    }
    if (tid < BN)            qsum[tid] = rsqrtf(fmaxf(qsum[tid] + qsum[128 + tid], 1e-12f));
    else if (tid < BN + BM)  ssum[tid - BN] = rsqrtf(fmaxf(ssum[tid - BN] + ssum[80 + tid - BN], 1e-12f));
    __syncthreads();

    // ---- epilogue: dist into smem (kg=0 only) ----
    if (kg == 0) {
        #pragma unroll
        for (int j = 0; j < 8; j++) {
            const int lc = wn * 64 + j * 8 + t * 2;
            #pragma unroll
            for (int half = 0; half < 2; half++) {
                const int lr = wm * 16 + g + half * 8;      // 0..79
                const float invs = ssum[lr];
                const int s = lr >> 4, l = lr & 15;
                #pragma unroll
                for (int e = 0; e < 2; e++) {
                    const int c = lc + e;                    // local col 0..127
                    const int qloc = c >> 4, m = c & 15;
                    const int pb = qloc * NS + s;            // 0..39
                    const float v = acc[j][half * 2 + e];
                    sDist[pb * PSTRIDE + (l << 4) + m] = 1.0f - v * invs * qsum[c];
                }
            }
        }
    }
    __syncthreads();

    // ---- soft-DTW: 80 threads, one (problem, direction) each ----
    if (tid < 80) {
        const int pb = tid >> 1, dir = tid & 1;
        const float* dm = sDist + pb * PSTRIDE;
        const int base = dir ? 255 : 0;
        const int sgn = dir ? -1 : 1;

        float prev[T_ + 2];
        prev[0] = 0.f;
        #pragma unroll
        for (int m = 1; m <= T_; m++) prev[m] = prev[m - 1] + dm[base + sgn * (m - 1)];
        prev[T_ + 1] = prev[T_];

        for (int l = 1; l < T_; l++) {
            const int rb = base + sgn * (l * 16);
            float drow[T_];
            #pragma unroll
            for (int m = 0; m < T_; m++) drow[m] = dm[rb + sgn * m];
            float left = 0.f;
            float dprev = prev[0];
            #pragma unroll
            for (int m = 1; m <= T_ + 1; m++) {
                const float up = prev[m];
                const float d = (m <= T_) ? drow[m - 1] : 0.f;
                float val;
                if (m == 1 || m == T_ + 1) val = softmin3(dprev, left, up) + d;
                else                        val = softmin2(dprev, left) + d;
                dprev = up;
                prev[m] = val;
                left = val;
            }
        }
        if (dir == 0) t1s[pb] = prev[T_ + 1];
        else          t2s[pb] = prev[T_ + 1];
    }
    __syncthreads();

    // ---- per-block outputs: tam + per-query CE term ----
    if (tid < 40) {
        const int qloc = tid / NS, s = tid % NS;
        const int row = b * NQ + nt * 8 + qloc;
        out[1 + row * NS + s] = 0.5f * (t1s[tid] + t2s[tid]);
    }
    if (tid < 8) {
        const int row = b * NQ + nt * 8 + tid;
        float t1[NS], t2[NS];
        #pragma unroll
        for (int s = 0; s < NS; s++) { t1[s] = t1s[tid * NS + s]; t2[s] = t2s[tid * NS + s]; }
        float mx1 = -t1[0], mx2 = -t2[0];
        #pragma unroll
        for (int s = 1; s < NS; s++) { mx1 = fmaxf(mx1, -t1[s]); mx2 = fmaxf(mx2, -t2[s]); }
        float se1 = 0.f, se2 = 0.f;
        #pragma unroll
        for (int s = 0; s < NS; s++) { se1 += __expf(-t1[s] - mx1); se2 += __expf(-t2[s] - mx2); }
        const int y = ys[row];
        g_rowterm[row] = (mx1 + __logf(se1) + t1[y]) + (mx2 + __logf(se2) + t2[y]);
    }

    // ---- last block computes the final loss ----
    __shared__ unsigned s_last;
    __shared__ float s_red[20];
    __threadfence();
    __syncthreads();
    if (tid == 0) s_last = (atomicAdd(&g_done, 1u) == 127u) ? 1u : 0u;
    __syncthreads();
    if (s_last) {
        float v = 0.f;
        if (tid < 512) v = g_rowterm[tid] + g_rowterm[tid + 512];
        #pragma unroll
        for (int o = 16; o; o >>= 1) v += __shfl_xor_sync(0xffffffffu, v, o);
        if (lane == 0 && wid < 16) s_red[wid] = v;
        __syncthreads();
        if (wid == 0) {
            float u = (lane < 16) ? s_red[lane] : 0.f;
            #pragma unroll
            for (int o = 8; o; o >>= 1) u += __shfl_xor_sync(0xffffffffu, u, o);
            if (lane == 0) { out[0] = 0.5f * u / (float)NROWS; g_done = 0u; }
        }
    }
}

// ---------------- launch ----------------
extern "C" void kernel_launch(void* const* d_in, const int* in_sizes, int n_in,
                              void* d_out, int out_size) {
    const float* supp  = (const float*)d_in[0];
    const float* query = (const float*)d_in[1];
    const int*   ys    = (const int*)d_in[2];
    float* out = (float*)d_out;

    static bool attr_set = false;
    if (!attr_set) {
        cudaFuncSetAttribute(gemm_dtw_kernel,
                             cudaFuncAttributeMaxDynamicSharedMemorySize, SMEM_BYTES);
        attr_set = true;
    }

    gemm_dtw_kernel<<<dim3(16, B_), GT, SMEM_BYTES>>>(supp, query, ys, out);
}